// round 7
// baseline (speedup 1.0000x reference)
#include <cuda_runtime.h>
#include <cstdint>
#include <math.h>

typedef unsigned long long ull;

#define HEADS   8
#define DHQK    32
#define DHV     32
#define BSZ     8
#define HALO    3
#define WIN     14
#define WIN2    196
#define QKVW    768
#define NPIX    4096
#define NBATCH  16
#define SCALE_QK 0.17677669529663687f

// Scratch: fused qkv per pixel, layout [b][pix][768]:
//   [0,256)   q  : channel = head*32 + d
//   [256,768) kv : channel = head*64 + d (k: d<32, v: d>=32)
__device__ float g_qkv[(size_t)NBATCH * NPIX * QKVW];

// ---------- packed f32x2 helpers ----------
__device__ __forceinline__ ull pk2(float lo, float hi) {
    ull r; asm("mov.b64 %0, {%1, %2};" : "=l"(r) : "f"(lo), "f"(hi)); return r;
}
__device__ __forceinline__ ull fma2(ull a, ull b, ull c) {
    ull d; asm("fma.rn.f32x2 %0, %1, %2, %3;" : "=l"(d) : "l"(a), "l"(b), "l"(c)); return d;
}
__device__ __forceinline__ float2 upk2(ull v) {
    float2 r; asm("mov.b64 {%0, %1}, %2;" : "=f"(r.x), "=f"(r.y) : "l"(v)); return r;
}

// smem geometry (shared by both paths; attn is the larger)
#define QT_ST 68
#define KT_ST 197
#define VS_ST 36
#define AT_SMEM_FLOATS (32 * QT_ST + 32 * KT_ST + WIN2 * VS_ST + 64 * WIN2)
#define AT_SMEM_BYTES  (AT_SMEM_FLOATS * 4)   // 112,320
// gemm path: As 2x2048 floats, Bs 2x2112 floats = 33,280 B (fits inside)
#define GA_BUF 2048
#define GB_BUF 2112

// =====================================================================
// device path 1: fused QKV projection GEMM tile (f32x2, double-buffered)
//   one call handles block (n0 = nt*128, mblk) — R6 body verbatim.
// =====================================================================
__device__ __forceinline__ void gemm_block(float* sm, int nt, int mblk,
                                           const float* __restrict__ x,
                                           const float* __restrict__ Wq,
                                           const float* __restrict__ Wkv) {
    float* As = sm;                 // [2][16*128]
    float* Bs = sm + 2 * GA_BUF;    // [2][16*132]

    const int n0   = nt * 128;
    const int b    = mblk >> 5;
    const int pix0 = (mblk & 31) << 7;

    const float* xb = x + ((size_t)b * 256) * NPIX + pix0;
    const float* Wb = (n0 < 256) ? (Wq + (size_t)n0 * 256)
                                 : (Wkv + (size_t)(n0 - 256) * 256);

    const int tid = threadIdx.x;
    const int tmg = tid >> 4;
    const int tng = tid & 15;

    const int la_c  = tid >> 5;
    const int la_m4 = (tid & 31) << 2;
    const int lb_o  = tid >> 1;
    const int lb_k8 = (tid & 1) << 3;

    ull acc[8][4];
    #pragma unroll
    for (int i = 0; i < 8; ++i)
        #pragma unroll
        for (int j = 0; j < 4; ++j) acc[i][j] = 0ull;

    #pragma unroll
    for (int i = 0; i < 2; ++i) {
        int c = la_c + i * 8;
        *(float4*)(&As[c * 128 + la_m4]) =
            *(const float4*)(xb + (size_t)c * NPIX + la_m4);
    }
    #pragma unroll
    for (int i = 0; i < 2; ++i) {
        float4 wv = *(const float4*)(Wb + (size_t)lb_o * 256 + lb_k8 + i * 4);
        Bs[(lb_k8 + i * 4 + 0) * 132 + lb_o] = wv.x;
        Bs[(lb_k8 + i * 4 + 1) * 132 + lb_o] = wv.y;
        Bs[(lb_k8 + i * 4 + 2) * 132 + lb_o] = wv.z;
        Bs[(lb_k8 + i * 4 + 3) * 132 + lb_o] = wv.w;
    }
    __syncthreads();

    for (int c = 0; c < 16; ++c) {
        const int cur = c & 1, nxt = cur ^ 1;

        float4 a_reg[2], b_reg[2];
        if (c < 15) {
            const int kc = (c + 1) * 16;
            #pragma unroll
            for (int i = 0; i < 2; ++i)
                a_reg[i] = *(const float4*)(xb + (size_t)(kc + la_c + i * 8) * NPIX + la_m4);
            #pragma unroll
            for (int i = 0; i < 2; ++i)
                b_reg[i] = *(const float4*)(Wb + (size_t)lb_o * 256 + kc + lb_k8 + i * 4);
        }

        const float* Ac = As + cur * GA_BUF;
        const float* Bc = Bs + cur * GB_BUF;
        #pragma unroll
        for (int kk = 0; kk < 16; ++kk) {
            float4 a0 = *(const float4*)(Ac + kk * 128 + tmg * 8);
            float4 a1 = *(const float4*)(Ac + kk * 128 + tmg * 8 + 4);
            float4 b0 = *(const float4*)(Bc + kk * 132 + tng * 4);
            float4 b1 = *(const float4*)(Bc + kk * 132 + 64 + tng * 4);
            ull bp0 = pk2(b0.x, b0.y), bp1 = pk2(b0.z, b0.w);
            ull bp2 = pk2(b1.x, b1.y), bp3 = pk2(b1.z, b1.w);
            float av[8] = {a0.x, a0.y, a0.z, a0.w, a1.x, a1.y, a1.z, a1.w};
            #pragma unroll
            for (int i = 0; i < 8; ++i) {
                ull ad = pk2(av[i], av[i]);
                acc[i][0] = fma2(ad, bp0, acc[i][0]);
                acc[i][1] = fma2(ad, bp1, acc[i][1]);
                acc[i][2] = fma2(ad, bp2, acc[i][2]);
                acc[i][3] = fma2(ad, bp3, acc[i][3]);
            }
        }

        if (c < 15) {
            float* An = As + nxt * GA_BUF;
            float* Bn = Bs + nxt * GB_BUF;
            #pragma unroll
            for (int i = 0; i < 2; ++i)
                *(float4*)(&An[(la_c + i * 8) * 128 + la_m4]) = a_reg[i];
            #pragma unroll
            for (int i = 0; i < 2; ++i) {
                Bn[(lb_k8 + i * 4 + 0) * 132 + lb_o] = b_reg[i].x;
                Bn[(lb_k8 + i * 4 + 1) * 132 + lb_o] = b_reg[i].y;
                Bn[(lb_k8 + i * 4 + 2) * 132 + lb_o] = b_reg[i].z;
                Bn[(lb_k8 + i * 4 + 3) * 132 + lb_o] = b_reg[i].w;
            }
        }
        __syncthreads();
    }

    const size_t mbase = (size_t)b * NPIX + pix0;
    #pragma unroll
    for (int i = 0; i < 8; ++i) {
        int m = tmg * 8 + i;
        float2 p0 = upk2(acc[i][0]), p1 = upk2(acc[i][1]);
        float2 p2 = upk2(acc[i][2]), p3 = upk2(acc[i][3]);
        float* op = g_qkv + (mbase + m) * QKVW + n0 + tng * 4;
        *(float4*)(op)      = make_float4(p0.x, p0.y, p1.x, p1.y);
        *(float4*)(op + 64) = make_float4(p2.x, p2.y, p3.x, p3.y);
    }
}

// =====================================================================
// device path 2: halo block attention tile (R6 body verbatim)
// =====================================================================
__device__ __forceinline__ void attn_block(float* sm, int nb, int h, int b,
                                           const float* __restrict__ pos_bias,
                                           float* __restrict__ out) {
    float* Qt = sm;
    float* Kt = sm + 32 * QT_ST;
    float* Vs = Kt + 32 * KT_ST;
    float* Ps = Vs + WIN2 * VS_ST;

    const int by = nb >> 3, bx = nb & 7;
    const int tid = threadIdx.x;
    const int w = tid >> 5, lane = tid & 31;
    const int w8 = w * 8;
    const float* qkv_b = g_qkv + (size_t)b * NPIX * QKVW;

    // ---- gather: K + V ----
    for (int idx = tid; idx < WIN2 * 8; idx += 256) {
        const int kk = idx >> 3, d4 = (idx & 7) << 2;
        const int wy = kk / WIN, wx = kk - wy * WIN;
        const int py = by * BSZ - HALO + wy, px = bx * BSZ - HALO + wx;
        const bool ok = ((unsigned)py < 64u) && ((unsigned)px < 64u);
        const float4 z4 = make_float4(0.f, 0.f, 0.f, 0.f);
        const float* src = qkv_b + (py * 64 + px) * QKVW + 256 + h * 64;
        float4 kv = ok ? *(const float4*)(src + d4) : z4;
        Kt[(d4 + 0) * KT_ST + kk] = kv.x;
        Kt[(d4 + 1) * KT_ST + kk] = kv.y;
        Kt[(d4 + 2) * KT_ST + kk] = kv.z;
        Kt[(d4 + 3) * KT_ST + kk] = kv.w;
        float4 vv = ok ? *(const float4*)(src + 32 + d4) : z4;
        *(float4*)(Vs + kk * VS_ST + d4) = vv;
    }
    // ---- gather: Q ----
    #pragma unroll
    for (int it = 0; it < 2; ++it) {
        const int idx = tid + it * 256;
        const int q4 = (idx >> 6) << 2, r = idx & 63;
        const int py = by * BSZ + (r >> 3), px = bx * BSZ + (r & 7);
        float4 qv = *(const float4*)(qkv_b + (py * 64 + px) * QKVW + h * DHQK + q4);
        Qt[(q4 + 0) * QT_ST + r] = qv.x;
        Qt[(q4 + 1) * QT_ST + r] = qv.y;
        Qt[(q4 + 2) * QT_ST + r] = qv.z;
        Qt[(q4 + 3) * QT_ST + r] = qv.w;
    }
    __syncthreads();      // the only barrier

    // ---- QK: rows-packed f32x2 ----
    ull s2[4][7];
    #pragma unroll
    for (int j = 0; j < 4; ++j)
        #pragma unroll
        for (int nc = 0; nc < 7; ++nc) s2[j][nc] = 0ull;

    #pragma unroll 4
    for (int d = 0; d < 32; ++d) {
        ull kv2[7];
        #pragma unroll
        for (int nc = 0; nc < 7; ++nc) {
            float kf = Kt[d * KT_ST + nc * 32 + lane];
            kv2[nc] = pk2(kf, kf);
        }
        float4 qa = *(const float4*)(Qt + d * QT_ST + w8);
        float4 qb = *(const float4*)(Qt + d * QT_ST + w8 + 4);
        ull q01 = pk2(qa.x, qa.y), q23 = pk2(qa.z, qa.w);
        ull q45 = pk2(qb.x, qb.y), q67 = pk2(qb.z, qb.w);
        #pragma unroll
        for (int nc = 0; nc < 7; ++nc) {
            s2[0][nc] = fma2(q01, kv2[nc], s2[0][nc]);
            s2[1][nc] = fma2(q23, kv2[nc], s2[1][nc]);
            s2[2][nc] = fma2(q45, kv2[nc], s2[2][nc]);
            s2[3][nc] = fma2(q67, kv2[nc], s2[3][nc]);
        }
    }

    // ---- bias + mask + softmax ----
    const float* pbase = pos_bias + (size_t)(h * 64 + w8) * WIN2;
    const float NEG = -1e30f;
    float inv_[8];
    #pragma unroll
    for (int j = 0; j < 4; ++j) {
        #pragma unroll
        for (int rr = 0; rr < 2; ++rr) {
            const int mi = 2 * j + rr;
            float s[7];
            #pragma unroll
            for (int nc = 0; nc < 7; ++nc) {
                float2 t = upk2(s2[j][nc]);
                float sv = rr ? t.y : t.x;
                int kk = nc * 32 + lane;
                s[nc] = (kk < WIN2) ? fmaf(sv, SCALE_QK, pbase[mi * WIN2 + kk]) : NEG;
            }
            float mx = s[0];
            #pragma unroll
            for (int nc = 1; nc < 7; ++nc) mx = fmaxf(mx, s[nc]);
            #pragma unroll
            for (int off = 16; off > 0; off >>= 1)
                mx = fmaxf(mx, __shfl_xor_sync(0xffffffffu, mx, off));
            float sum = 0.f;
            #pragma unroll
            for (int nc = 0; nc < 7; ++nc) {
                float e = __expf(s[nc] - mx);
                s[nc] = e;
                sum += e;
            }
            #pragma unroll
            for (int off = 16; off > 0; off >>= 1)
                sum += __shfl_xor_sync(0xffffffffu, sum, off);
            inv_[mi] = 1.f / sum;
            float* prow = Ps + (w8 + mi) * WIN2;
            #pragma unroll
            for (int nc = 0; nc < 6; ++nc)
                prow[nc * 32 + lane] = s[nc];
            if (lane < 4) prow[192 + lane] = s[6];
        }
    }

    // ---- PV ----
    ull acc2[8];
    #pragma unroll
    for (int mi = 0; mi < 8; ++mi) acc2[mi] = 0ull;
    const float* prow = Ps + w8 * WIN2;
    #pragma unroll 2
    for (int k4 = 0; k4 < WIN2 / 4; ++k4) {
        float v0 = Vs[(4 * k4 + 0) * VS_ST + lane];
        float v1 = Vs[(4 * k4 + 1) * VS_ST + lane];
        float v2 = Vs[(4 * k4 + 2) * VS_ST + lane];
        float v3 = Vs[(4 * k4 + 3) * VS_ST + lane];
        ull va = pk2(v0, v1), vb = pk2(v2, v3);
        #pragma unroll
        for (int mi = 0; mi < 8; ++mi) {
            float4 p = *(const float4*)(prow + mi * WIN2 + 4 * k4);
            acc2[mi] = fma2(pk2(p.x, p.y), va, acc2[mi]);
            acc2[mi] = fma2(pk2(p.z, p.w), vb, acc2[mi]);
        }
    }

    // ---- epilogue ----
    float o[8];
    #pragma unroll
    for (int mi = 0; mi < 8; ++mi) {
        float2 t = upk2(acc2[mi]);
        o[mi] = (t.x + t.y) * inv_[mi];
    }
    float* op = out + (((size_t)(b * HEADS + h) * DHV + lane) * 64 + by * BSZ + w) * 64
                    + bx * BSZ;
    *(float4*)(op)     = make_float4(o[0], o[1], o[2], o[3]);
    *(float4*)(op + 4) = make_float4(o[4], o[5], o[6], o[7]);
}

// =====================================================================
// merged pipelined kernel: one launch carries attn blocks for batches
//   [attn_b0, attn_b0+..) and gemm blocks for [gemm_b0, ..), interleaved
//   8:3 within blockIdx so both kinds co-reside on each SM.
//   attn per batch = 512 blocks; gemm per batch = 192 blocks.
// =====================================================================
__global__ __launch_bounds__(256, 2) void mix_kernel(
        const float* __restrict__ x,  const float* __restrict__ Wq,
        const float* __restrict__ Wkv, const float* __restrict__ pos_bias,
        float* __restrict__ out,
        int attn_b0, int attn_blocks, int gemm_b0, int gemm_blocks) {
    extern __shared__ float sm[];
    const int bid = blockIdx.x;

    int is_attn, sub;
    if (attn_blocks > 0 && gemm_blocks > 0) {
        // 8 attn : 3 gemm per group of 11 (2048 + 768 = 11 * 256)
        const int grp = bid / 11, t = bid - grp * 11;
        if (t < 8) { is_attn = 1; sub = grp * 8 + t; }
        else       { is_attn = 0; sub = grp * 3 + (t - 8); }
    } else if (attn_blocks > 0) {
        is_attn = 1; sub = bid;
    } else {
        is_attn = 0; sub = bid;
    }

    if (is_attn) {
        const int b  = attn_b0 + (sub >> 9);
        const int h  = (sub >> 6) & 7;
        const int nb = sub & 63;
        attn_block(sm, nb, h, b, pos_bias, out);
    } else {
        const int nt   = sub % 6;
        const int mblk = (gemm_b0 << 5) + sub / 6;
        gemm_block(sm, nt, mblk, x, Wq, Wkv);
    }
}

// =====================================================================
extern "C" void kernel_launch(void* const* d_in, const int* in_sizes, int n_in,
                              void* d_out, int out_size) {
    const float* x   = (const float*)d_in[0];
    const float* Wq  = (const float*)d_in[1];
    const float* Wkv = (const float*)d_in[2];
    const float* pb  = (const float*)d_in[3];
    float* out = (float*)d_out;

    cudaFuncSetAttribute(mix_kernel,
                         cudaFuncAttributeMaxDynamicSharedMemorySize, AT_SMEM_BYTES);

    // 5-step batch pipeline: gemm quarter g, overlapped with attn quarter g-1
    // S0: gemm b0..3 only (768 blocks)
    mix_kernel<<<768, 256, AT_SMEM_BYTES>>>(x, Wq, Wkv, pb, out, 0, 0, 0, 768);
    // S1..S3: attn(prev quarter) + gemm(next quarter), interleaved 8:3
    for (int s = 0; s < 3; ++s)
        mix_kernel<<<2816, 256, AT_SMEM_BYTES>>>(x, Wq, Wkv, pb, out,
                                                 4 * s, 2048, 4 * (s + 1), 768);
    // S4: attn b12..15 only (2048 blocks)
    mix_kernel<<<2048, 256, AT_SMEM_BYTES>>>(x, Wq, Wkv, pb, out, 12, 2048, 0, 0);
}